// round 1
// baseline (speedup 1.0000x reference)
#include <cuda_runtime.h>
#include <math.h>

#define SQ 2048
#define DM 2048
#define NH 16
#define NKV 8
#define HD 128
#define TOPK 40
#define SCALE 0.08838834764831845f  // 128^-0.5

// ---------------- scratch (device globals; no allocations allowed) ----------
__device__ float g_q [(size_t)SQ * DM];        // q projection   [S, H*HD]
__device__ float g_k [(size_t)SQ * NKV * HD];  // k projection   [S, HKV*HD]
__device__ float g_v [(size_t)SQ * NKV * HD];  // v projection
__device__ float g_qr[(size_t)NH  * SQ * HD];  // q rotated      [H, S, HD]
__device__ float g_kr[(size_t)NKV * SQ * HD];  // k rotated      [HKV, S, HD]
__device__ float g_vr[(size_t)NKV * SQ * HD];  // v transposed   [HKV, S, HD]
__device__ float g_sc[(size_t)NH * SQ * SQ];   // scores         [H, S, S]  (256 MB)
__device__ float g_at[(size_t)SQ * DM];        // attention out  [S, H*HD]

// ---------------- GEMM: C[M,N] = alpha * A[M,K] @ B[N,K]^T (row-major) ------
// batched over blockIdx.z with element strides; B advances every bDiv z-steps.
__global__ __launch_bounds__(256) void gemm_nt(
    const float* __restrict__ A, const float* __restrict__ B,
    float* __restrict__ C, int M, int N, int K,
    long sA, long sB, long sC, float alpha, int bDiv)
{
    __shared__ float As[16][128];
    __shared__ float Bs[16][128];
    const float* Az = A + (long)blockIdx.z * sA;
    const float* Bz = B + (long)(blockIdx.z / bDiv) * sB;
    float*       Cz = C + (long)blockIdx.z * sC;

    int brow = blockIdx.y * 128;
    int bcol = blockIdx.x * 128;
    int tid  = threadIdx.x;
    int ty   = tid >> 4;     // 0..15
    int tx   = tid & 15;     // 0..15

    float acc[8][8];
#pragma unroll
    for (int i = 0; i < 8; i++)
#pragma unroll
        for (int j = 0; j < 8; j++) acc[i][j] = 0.f;

    for (int k0 = 0; k0 < K; k0 += 16) {
#pragma unroll
        for (int it = 0; it < 2; it++) {
            int idx = tid + it * 256;          // 0..511
            int r   = idx >> 2;                // 0..127
            int c   = (idx & 3) * 4;           // 0,4,8,12
            float4 va = *(const float4*)&Az[(long)(brow + r) * K + k0 + c];
            As[c + 0][r] = va.x; As[c + 1][r] = va.y;
            As[c + 2][r] = va.z; As[c + 3][r] = va.w;
            float4 vb = *(const float4*)&Bz[(long)(bcol + r) * K + k0 + c];
            Bs[c + 0][r] = vb.x; Bs[c + 1][r] = vb.y;
            Bs[c + 2][r] = vb.z; Bs[c + 3][r] = vb.w;
        }
        __syncthreads();
#pragma unroll
        for (int kk = 0; kk < 16; kk++) {
            float a[8], b[8];
#pragma unroll
            for (int i = 0; i < 8; i++) a[i] = As[kk][ty * 8 + i];
#pragma unroll
            for (int j = 0; j < 8; j++) b[j] = Bs[kk][tx * 8 + j];
#pragma unroll
            for (int i = 0; i < 8; i++)
#pragma unroll
                for (int j = 0; j < 8; j++) acc[i][j] += a[i] * b[j];
        }
        __syncthreads();
    }
#pragma unroll
    for (int i = 0; i < 8; i++) {
        long rr = brow + ty * 8 + i;
#pragma unroll
        for (int j = 0; j < 8; j++)
            Cz[rr * N + bcol + tx * 8 + j] = alpha * acc[i][j];
    }
}

// ---------------- block reduction helper (128 threads) ----------------------
__device__ __forceinline__ float blockSum128(float v, float* red) {
#pragma unroll
    for (int o = 16; o > 0; o >>= 1) v += __shfl_down_sync(0xffffffffu, v, o);
    if ((threadIdx.x & 31) == 0) red[threadIdx.x >> 5] = v;
    __syncthreads();
    return red[0] + red[1] + red[2] + red[3];
}

// ---------------- rms-norm + rope for Q:  g_q -> g_qr [H,S,HD] --------------
__global__ void rope_q_kernel(const float* __restrict__ cosb,
                              const float* __restrict__ sinb,
                              const float* __restrict__ w)
{
    int s = blockIdx.x, h = blockIdx.y, d = threadIdx.x;
    __shared__ float red[4];
    __shared__ float sh[HD];
    float v = g_q[(long)s * DM + h * HD + d];
    float ss = blockSum128(v * v, red);
    float inv = rsqrtf(ss * (1.0f / HD) + 1e-6f);
    float qn = v * inv * w[d];
    sh[d] = qn;
    __syncthreads();
    float rot = (d < 64) ? -sh[d + 64] : sh[d - 64];
    g_qr[((long)h * SQ + s) * HD + d] = qn * cosb[s * HD + d] + rot * sinb[s * HD + d];
}

// ---------------- rms-norm + rope for K, transpose V ------------------------
__global__ void rope_kv_kernel(const float* __restrict__ cosb,
                               const float* __restrict__ sinb,
                               const float* __restrict__ w)
{
    int s = blockIdx.x, h = blockIdx.y, d = threadIdx.x;
    __shared__ float red[4];
    __shared__ float sh[HD];
    float v = g_k[(long)s * (NKV * HD) + h * HD + d];
    float ss = blockSum128(v * v, red);
    float inv = rsqrtf(ss * (1.0f / HD) + 1e-6f);
    float kn = v * inv * w[d];
    sh[d] = kn;
    __syncthreads();
    float rot = (d < 64) ? -sh[d + 64] : sh[d - 64];
    g_kr[((long)h * SQ + s) * HD + d] = kn * cosb[s * HD + d] + rot * sinb[s * HD + d];
    g_vr[((long)h * SQ + s) * HD + d] = g_v[(long)s * (NKV * HD) + h * HD + d];
}

// ---------------- monotone float->uint key ----------------------------------
__device__ __forceinline__ unsigned fkey(float f) {
    unsigned u = __float_as_uint(f);
    return (u & 0x80000000u) ? ~u : (u | 0x80000000u);
}

// ---------------- exact top-40 threshold + softmax + sparse PV --------------
// One block (128 threads) per (row, head). Scores row = 2048 values,
// 16 per thread (register-resident).
__global__ void attn_select_kernel()
{
    int row = blockIdx.x, h = blockIdx.y;
    int kvh = h >> 1;   // rep = H/HKV = 2
    int t = threadIdx.x;
    const float* srow = g_sc + ((size_t)h * SQ + row) * SQ;

    float    val[16];
    unsigned key[16];
    float lmax = -3.4e38f;
#pragma unroll
    for (int i = 0; i < 16; i++) {
        float v = srow[t + i * 128];
        val[i] = v;
        key[i] = fkey(v);
        lmax = fmaxf(lmax, v);
    }

    __shared__ float redf[4];
    __shared__ int   redc[4];

    // row max (global max is always kept: it is in the top-40)
    float m = lmax;
#pragma unroll
    for (int o = 16; o > 0; o >>= 1) m = fmaxf(m, __shfl_down_sync(0xffffffffu, m, o));
    if ((t & 31) == 0) redf[t >> 5] = m;
    __syncthreads();
    float rowmax = fmaxf(fmaxf(redf[0], redf[1]), fmaxf(redf[2], redf[3]));

    // binary search for key of the 40th-largest value:
    // lo = max key with count(key >= lo) >= TOPK  (exact, incl. ties)
    unsigned lo = 0u, hi = 0xFFFFFFFFu;
    while (lo < hi) {
        unsigned mid = lo + ((hi - lo) >> 1) + 1u;   // in (lo, hi]
        int c = 0;
#pragma unroll
        for (int i = 0; i < 16; i++) c += (key[i] >= mid);
#pragma unroll
        for (int o = 16; o > 0; o >>= 1) c += __shfl_down_sync(0xffffffffu, c, o);
        __syncthreads();                 // protect redc from previous iter
        if ((t & 31) == 0) redc[t >> 5] = c;
        __syncthreads();
        int cnt = redc[0] + redc[1] + redc[2] + redc[3];
        if (cnt >= TOPK) lo = mid; else hi = mid - 1u;
    }
    unsigned thr = lo;

    // deterministic compaction of kept indices (keep = score>=thr  OR diagonal)
    unsigned mask = 0;
#pragma unroll
    for (int i = 0; i < 16; i++) {
        int j = t + i * 128;
        if (key[i] >= thr || j == row) mask |= (1u << i);
    }
    int mc = __popc(mask);

    __shared__ int cnts[129];
    cnts[t] = mc;
    __syncthreads();
    if (t == 0) {
        int a = 0;
        for (int x = 0; x < 128; x++) { int c = cnts[x]; cnts[x] = a; a += c; }
        cnts[128] = a;
    }
    __syncthreads();
    int total = cnts[128];
    if (total > 256) total = 256;   // ties beyond capacity: astronomically unlikely

    __shared__ int   sIdx[256];
    __shared__ float sP[256];
    {
        int p = cnts[t];
#pragma unroll
        for (int i = 0; i < 16; i++) {
            if (mask & (1u << i)) {
                if (p < 256) {
                    sIdx[p] = t + i * 128;
                    sP[p]   = __expf(val[i] - rowmax);   // masked-out cols underflow to exactly 0 in ref
                }
                p++;
            }
        }
    }
    __syncthreads();

    // denominator
    float ps = 0.f;
    for (int p = t; p < total; p += 128) ps += sP[p];
#pragma unroll
    for (int o = 16; o > 0; o >>= 1) ps += __shfl_down_sync(0xffffffffu, ps, o);
    if ((t & 31) == 0) redf[t >> 5] = ps;
    __syncthreads();
    float denom = redf[0] + redf[1] + redf[2] + redf[3];

    // sparse PV: out[d] = sum_kept p * v[idx][d] / denom   (coalesced v rows)
    float acc = 0.f;
    for (int p = 0; p < total; p++)
        acc += sP[p] * g_vr[((size_t)kvh * SQ + sIdx[p]) * HD + t];

    g_at[(size_t)row * DM + h * HD + t] = acc / denom;
}

// ---------------- launch -----------------------------------------------------
extern "C" void kernel_launch(void* const* d_in, const int* in_sizes, int n_in,
                              void* d_out, int out_size)
{
    const float* x    = (const float*)d_in[0];
    const float* cosb = (const float*)d_in[1];
    const float* sinb = (const float*)d_in[2];
    const float* Wq   = (const float*)d_in[3];
    const float* Wk   = (const float*)d_in[4];
    const float* Wv   = (const float*)d_in[5];
    const float* Wo   = (const float*)d_in[6];
    const float* qw   = (const float*)d_in[7];
    const float* kw   = (const float*)d_in[8];
    float* out = (float*)d_out;

    float *pq, *pk, *pv, *pqr, *pkr, *psc, *pat;
    cudaGetSymbolAddress((void**)&pq,  g_q);
    cudaGetSymbolAddress((void**)&pk,  g_k);
    cudaGetSymbolAddress((void**)&pv,  g_v);
    cudaGetSymbolAddress((void**)&pqr, g_qr);
    cudaGetSymbolAddress((void**)&pkr, g_kr);
    cudaGetSymbolAddress((void**)&psc, g_sc);
    cudaGetSymbolAddress((void**)&pat, g_at);

    dim3 blk(256);

    // QKV projections:  [S,D] @ W^T
    gemm_nt<<<dim3(DM / 128, SQ / 128, 1), blk>>>(x, Wq, pq, SQ, DM, DM, 0, 0, 0, 1.f, 1);
    gemm_nt<<<dim3((NKV * HD) / 128, SQ / 128, 1), blk>>>(x, Wk, pk, SQ, NKV * HD, DM, 0, 0, 0, 1.f, 1);
    gemm_nt<<<dim3((NKV * HD) / 128, SQ / 128, 1), blk>>>(x, Wv, pv, SQ, NKV * HD, DM, 0, 0, 0, 1.f, 1);

    // rms-norm + rope (+ v transpose)
    rope_q_kernel <<<dim3(SQ, NH),  128>>>(cosb, sinb, qw);
    rope_kv_kernel<<<dim3(SQ, NKV), 128>>>(cosb, sinb, kw);

    // scores = SCALE * q @ k^T, batched over heads (kv head = z/2)
    gemm_nt<<<dim3(SQ / 128, SQ / 128, NH), blk>>>(
        pqr, pkr, psc, SQ, SQ, HD,
        (long)SQ * HD, (long)SQ * HD, (long)SQ * SQ, SCALE, 2);

    // exact top-40 threshold + softmax + sparse PV
    attn_select_kernel<<<dim3(SQ, NH), 128>>>();

    // output projection
    gemm_nt<<<dim3(DM / 128, SQ / 128, 1), blk>>>(pat, Wo, out, SQ, DM, DM, 0, 0, 0, 1.f, 1);
}

// round 5
// speedup vs baseline: 1.1622x; 1.1622x over previous
#include <cuda_runtime.h>
#include <cuda_bf16.h>
#include <math.h>
#include <stdint.h>

typedef __nv_bfloat16 bf16;

#define SQ 2048
#define DM 2048
#define NH 16
#define NKV 8
#define HD 128
#define TOPK 40
#define SCALE 0.08838834764831845f  // 128^-0.5
#define EPS_BAND 1e-3f

#define K3P (3*DM)   // 6144: triple-K (V, O projections)
#define K3S (3*HD)   // 384:  triple-K (score screening)

// ---------------- scratch (device globals; no allocations allowed) ----------
__device__ float g_q  [(size_t)SQ * DM];          // q projection (fp32, bit = round1)
__device__ float g_k  [(size_t)SQ * NKV * HD];    // k projection (fp32, bit = round1)
__device__ float g_v  [(size_t)SQ * NKV * HD];    // v projection (HMMA, value-level)
__device__ float g_qr [(size_t)NH  * SQ * HD];    // q roped fp32 [H,S,HD]   (bit = round1)
__device__ float g_kr [(size_t)NKV * SQ * HD];    // k roped fp32 [HKV,S,HD] (bit = round1)
__device__ float g_sc [(size_t)NH * SQ * SQ];     // approx scores (256 MB)
__device__ bf16  g_x3 [(size_t)SQ * K3P];
__device__ bf16  g_wv3[(size_t)(NKV*HD) * K3P];
__device__ bf16  g_wo3[(size_t)DM * K3P];
__device__ bf16  g_qr3[(size_t)NH  * SQ * K3S];   // bf16x3 A-type roped q
__device__ bf16  g_kr3[(size_t)NKV * SQ * K3S];   // bf16x3 B-type roped k
__device__ bf16  g_at3[(size_t)SQ * K3P];         // attention out, bf16x3 A-type

// ============ fp32 GEMM (ROUND-1 VERBATIM — bit-exactness depends on it) ====
__global__ __launch_bounds__(256) void gemm_nt(
    const float* __restrict__ A, const float* __restrict__ B,
    float* __restrict__ C, int M, int N, int K,
    long sA, long sB, long sC, float alpha, int bDiv)
{
    __shared__ float As[16][128];
    __shared__ float Bs[16][128];
    const float* Az = A + (long)blockIdx.z * sA;
    const float* Bz = B + (long)(blockIdx.z / bDiv) * sB;
    float*       Cz = C + (long)blockIdx.z * sC;

    int brow = blockIdx.y * 128;
    int bcol = blockIdx.x * 128;
    int tid  = threadIdx.x;
    int ty   = tid >> 4;
    int tx   = tid & 15;

    float acc[8][8];
#pragma unroll
    for (int i = 0; i < 8; i++)
#pragma unroll
        for (int j = 0; j < 8; j++) acc[i][j] = 0.f;

    for (int k0 = 0; k0 < K; k0 += 16) {
#pragma unroll
        for (int it = 0; it < 2; it++) {
            int idx = tid + it * 256;
            int r   = idx >> 2;
            int c   = (idx & 3) * 4;
            float4 va = *(const float4*)&Az[(long)(brow + r) * K + k0 + c];
            As[c + 0][r] = va.x; As[c + 1][r] = va.y;
            As[c + 2][r] = va.z; As[c + 3][r] = va.w;
            float4 vb = *(const float4*)&Bz[(long)(bcol + r) * K + k0 + c];
            Bs[c + 0][r] = vb.x; Bs[c + 1][r] = vb.y;
            Bs[c + 2][r] = vb.z; Bs[c + 3][r] = vb.w;
        }
        __syncthreads();
#pragma unroll
        for (int kk = 0; kk < 16; kk++) {
            float a[8], b[8];
#pragma unroll
            for (int i = 0; i < 8; i++) a[i] = As[kk][ty * 8 + i];
#pragma unroll
            for (int j = 0; j < 8; j++) b[j] = Bs[kk][tx * 8 + j];
#pragma unroll
            for (int i = 0; i < 8; i++)
#pragma unroll
                for (int j = 0; j < 8; j++) acc[i][j] += a[i] * b[j];
        }
        __syncthreads();
    }
#pragma unroll
    for (int i = 0; i < 8; i++) {
        long rr = brow + ty * 8 + i;
#pragma unroll
        for (int j = 0; j < 8; j++)
            Cz[rr * N + bcol + tx * 8 + j] = alpha * acc[i][j];
    }
}

// ================= HMMA helpers =============================================
__device__ __forceinline__ uint32_t smem_u32(const void* p) {
    uint32_t a;
    asm("{ .reg .u64 t; cvta.to.shared.u64 t, %1; cvt.u32.u64 %0, t; }" : "=r"(a) : "l"(p));
    return a;
}
__device__ __forceinline__ void ldmatrix_x4(uint32_t* r, uint32_t addr) {
    asm volatile("ldmatrix.sync.aligned.m8n8.x4.shared.b16 {%0,%1,%2,%3}, [%4];"
        : "=r"(r[0]), "=r"(r[1]), "=r"(r[2]), "=r"(r[3]) : "r"(addr));
}
__device__ __forceinline__ void mma16816(float* c, const uint32_t* a, const uint32_t* b) {
    asm volatile(
        "mma.sync.aligned.m16n8k16.row.col.f32.bf16.bf16.f32 "
        "{%0,%1,%2,%3}, {%4,%5,%6,%7}, {%8,%9}, {%0,%1,%2,%3};"
        : "+f"(c[0]), "+f"(c[1]), "+f"(c[2]), "+f"(c[3])
        : "r"(a[0]), "r"(a[1]), "r"(a[2]), "r"(a[3]), "r"(b[0]), "r"(b[1]));
}
__device__ __forceinline__ uint32_t sw128(uint32_t bo) { return bo ^ ((bo >> 3) & 0x70); }

// ================= bf16x3 GEMM via mma.sync (HMMA) ==========================
#define OFF_A0 0u
#define OFF_B0 16384u
#define OFF_A1 32768u
#define OFF_B1 49152u
#define GEMM_SMEM (4*16384 + 256)

__device__ __forceinline__ void ldg_tile(uint4* r, const bf16* __restrict__ src,
                                         long row0, int k0, int ld, int tid) {
#pragma unroll
    for (int it = 0; it < 4; it++) {
        int idx = tid + it * 256;
        int rr  = idx >> 3;
        int c16 = (idx & 7) * 16;
        r[it] = *(const uint4*)((const char*)(src + (row0 + rr) * (long)ld + k0) + c16);
    }
}
__device__ __forceinline__ void sts_tile(char* sm, uint32_t off, const uint4* r, int tid) {
#pragma unroll
    for (int it = 0; it < 4; it++) {
        int idx = tid + it * 256;
        int rr  = idx >> 3;
        int c16 = (idx & 7) * 16;
        *(uint4*)(sm + off + sw128((uint32_t)(rr * 128 + c16))) = r[it];
    }
}

__global__ __launch_bounds__(256, 1) void gemm3_nt(
    const bf16* __restrict__ A, const bf16* __restrict__ B, float* __restrict__ C,
    int N, int K3, long sA, long sB, long sC, float alpha, int bDiv)
{
    extern __shared__ char smraw[];
    uint32_t raw  = smem_u32(smraw);
    uint32_t base = (raw + 127u) & ~127u;
    char* sm = smraw + (base - raw);

    const bf16* Az = A + (long)blockIdx.z * sA;
    const bf16* Bz = B + (long)(blockIdx.z / bDiv) * sB;
    float*      Cz = C + (long)blockIdx.z * sC;
    long brow = (long)blockIdx.y * 128;
    long bcol = (long)blockIdx.x * 128;
    int tid  = threadIdx.x;
    int lane = tid & 31;
    int wid  = tid >> 5;
    int wm   = wid & 3;
    int wn   = wid >> 2;

    float acc[2][8][4];
#pragma unroll
    for (int i = 0; i < 2; i++)
#pragma unroll
        for (int j = 0; j < 8; j++)
#pragma unroll
            for (int q = 0; q < 4; q++) acc[i][j][q] = 0.f;

    int NC = K3 / 64;
    uint4 rA[4], rB[4];

    ldg_tile(rA, Az, brow, 0, K3, tid);
    ldg_tile(rB, Bz, bcol, 0, K3, tid);
    sts_tile(sm, OFF_A0, rA, tid);
    sts_tile(sm, OFF_B0, rB, tid);
    __syncthreads();

    int aRow = wm * 32 + (lane & 15);
    int aCol = (lane >> 4) * 16;
    int bRow = wn * 64 + ((lane >> 4) << 3) + (lane & 7);
    int bCol = ((lane >> 3) & 1) * 16;

    for (int c = 0; c < NC; c++) {
        int b = c & 1;
        uint32_t smA = base + (b ? OFF_A1 : OFF_A0);
        uint32_t smB = base + (b ? OFF_B1 : OFF_B0);

        bool more = (c + 1 < NC);
        if (more) {
            ldg_tile(rA, Az, brow, (c + 1) * 64, K3, tid);
            ldg_tile(rB, Bz, bcol, (c + 1) * 64, K3, tid);
        }

#pragma unroll
        for (int ks = 0; ks < 4; ks++) {
            uint32_t a[2][4];
#pragma unroll
            for (int mt = 0; mt < 2; mt++) {
                uint32_t bo = (uint32_t)((aRow + mt * 16) * 128 + aCol + ks * 32);
                ldmatrix_x4(a[mt], smA + sw128(bo));
            }
            uint32_t bb[4][4];
#pragma unroll
            for (int p = 0; p < 4; p++) {
                uint32_t bo = (uint32_t)((bRow + p * 16) * 128 + bCol + ks * 32);
                ldmatrix_x4(bb[p], smB + sw128(bo));
            }
#pragma unroll
            for (int mt = 0; mt < 2; mt++)
#pragma unroll
                for (int nt = 0; nt < 8; nt++)
                    mma16816(acc[mt][nt], a[mt], &bb[nt >> 1][(nt & 1) * 2]);
        }

        if (more) {
            int nb = b ^ 1;
            sts_tile(sm, nb ? OFF_A1 : OFF_A0, rA, tid);
            sts_tile(sm, nb ? OFF_B1 : OFF_B0, rB, tid);
        }
        __syncthreads();
    }

    long r0 = brow + wm * 32 + (lane >> 2);
    long c0 = bcol + wn * 64 + (lane & 3) * 2;
#pragma unroll
    for (int mt = 0; mt < 2; mt++) {
#pragma unroll
        for (int nt = 0; nt < 8; nt++) {
            long rr = r0 + mt * 16;
            long cc = c0 + nt * 8;
            float2 v0 = make_float2(alpha * acc[mt][nt][0], alpha * acc[mt][nt][1]);
            float2 v1 = make_float2(alpha * acc[mt][nt][2], alpha * acc[mt][nt][3]);
            *(float2*)(Cz + rr * N + cc)       = v0;
            *(float2*)(Cz + (rr + 8) * N + cc) = v1;
        }
    }
}

// ================= fp32 -> bf16x3 limb conversion ===========================
// A-type row: [h1 | h1 | h2]    B-type row: [h1 | h2 | h1]
__global__ void conv3_kernel(const float4* __restrict__ src, bf16* __restrict__ dst,
                             long n4, int Kq, int isA)
{
    long i = (long)blockIdx.x * blockDim.x + threadIdx.x;
    if (i >= n4) return;
    long r  = i / Kq;
    int  c4 = (int)(i - r * Kq) * 4;
    int  K  = Kq * 4;
    float4 f = src[i];
    union { bf16 h[4]; uint2 u; } H1, H2;
    float fa[4] = {f.x, f.y, f.z, f.w};
#pragma unroll
    for (int j = 0; j < 4; j++) {
        H1.h[j] = __float2bfloat16(fa[j]);
        H2.h[j] = __float2bfloat16(fa[j] - __bfloat162float(H1.h[j]));
    }
    bf16* d = dst + r * (long)(3 * K) + c4;
    *(uint2*)(d)         = H1.u;
    *(uint2*)(d + K)     = isA ? H1.u : H2.u;
    *(uint2*)(d + 2 * K) = isA ? H2.u : H1.u;
}

// ================= rms-norm + rope (fp32 bit = round1, + limb emit) =========
__device__ __forceinline__ float blockSum128(float v, float* red) {
#pragma unroll
    for (int o = 16; o > 0; o >>= 1) v += __shfl_down_sync(0xffffffffu, v, o);
    if ((threadIdx.x & 31) == 0) red[threadIdx.x >> 5] = v;
    __syncthreads();
    return red[0] + red[1] + red[2] + red[3];
}

__global__ void rope_q_kernel(const float* __restrict__ cosb,
                              const float* __restrict__ sinb,
                              const float* __restrict__ w)
{
    int s = blockIdx.x, h = blockIdx.y, d = threadIdx.x;
    __shared__ float red[4];
    __shared__ float sh[HD];
    float v = g_q[(long)s * DM + h * HD + d];
    float ss = blockSum128(v * v, red);
    float inv = rsqrtf(ss * (1.0f / HD) + 1e-6f);
    float qn = v * inv * w[d];
    sh[d] = qn;
    __syncthreads();
    float rot = (d < 64) ? -sh[d + 64] : sh[d - 64];
    float f = qn * cosb[s * HD + d] + rot * sinb[s * HD + d];
    g_qr[((long)h * SQ + s) * HD + d] = f;                      // fp32 (bit = round1)
    bf16 h1 = __float2bfloat16(f);
    bf16 h2 = __float2bfloat16(f - __bfloat162float(h1));
    bf16* dq = g_qr3 + ((size_t)h * SQ + s) * K3S;
    dq[d] = h1; dq[HD + d] = h1; dq[2 * HD + d] = h2;           // A-type
}

__global__ void rope_k_kernel(const float* __restrict__ cosb,
                              const float* __restrict__ sinb,
                              const float* __restrict__ w)
{
    int s = blockIdx.x, h = blockIdx.y, d = threadIdx.x;
    __shared__ float red[4];
    __shared__ float sh[HD];
    float v = g_k[(long)s * (NKV * HD) + h * HD + d];
    float ss = blockSum128(v * v, red);
    float inv = rsqrtf(ss * (1.0f / HD) + 1e-6f);
    float kn = v * inv * w[d];
    sh[d] = kn;
    __syncthreads();
    float rot = (d < 64) ? -sh[d + 64] : sh[d - 64];
    float f = kn * cosb[s * HD + d] + rot * sinb[s * HD + d];
    g_kr[((long)h * SQ + s) * HD + d] = f;                      // fp32 (bit = round1)
    bf16 h1 = __float2bfloat16(f);
    bf16 h2 = __float2bfloat16(f - __bfloat162float(h1));
    bf16* dk = g_kr3 + ((size_t)h * SQ + s) * K3S;
    dk[d] = h1; dk[HD + d] = h2; dk[2 * HD + d] = h1;           // B-type
}

// ================= screening + exact rescore + softmax + sparse PV ==========
__device__ __forceinline__ unsigned fkey(float f) {
    unsigned u = __float_as_uint(f);
    return (u & 0x80000000u) ? ~u : (u | 0x80000000u);
}
__device__ __forceinline__ float unfkey(unsigned u) {
    unsigned v = (u & 0x80000000u) ? (u & 0x7FFFFFFFu) : ~u;
    return __uint_as_float(v);
}

#define CAP 256

__global__ void attn_select_kernel()
{
    int row = blockIdx.x, h = blockIdx.y;
    int kvh = h >> 1;
    int t = threadIdx.x;
    const float* srow = g_sc + ((size_t)h * SQ + row) * SQ;

    float    val[16];
    unsigned key[16];
#pragma unroll
    for (int i = 0; i < 16; i++) {
        float v = srow[t + i * 128];
        val[i] = v;
        key[i] = fkey(v);
    }

    __shared__ float redf[4];
    __shared__ int   redc[4];

    // --- approx 40th-largest key (binary search, exact w.r.t. approx scores)
    unsigned lo = 0u, hi = 0xFFFFFFFFu;
    while (lo < hi) {
        unsigned mid = lo + ((hi - lo) >> 1) + 1u;
        int c = 0;
#pragma unroll
        for (int i = 0; i < 16; i++) c += (key[i] >= mid);
#pragma unroll
        for (int o = 16; o > 0; o >>= 1) c += __shfl_down_sync(0xffffffffu, c, o);
        __syncthreads();
        if ((t & 31) == 0) redc[t >> 5] = c;
        __syncthreads();
        int cnt = redc[0] + redc[1] + redc[2] + redc[3];
        if (cnt >= TOPK) lo = mid; else hi = mid - 1u;
    }
    float band = unfkey(lo) - EPS_BAND;

    // --- band mask + deterministic compaction
    unsigned mask = 0;
#pragma unroll
    for (int i = 0; i < 16; i++) {
        int j = t + i * 128;
        if (val[i] >= band || j == row) mask |= (1u << i);
    }
    int mc = __popc(mask);

    __shared__ int cnts[129];
    cnts[t] = mc;
    __syncthreads();
    if (t == 0) {
        int a = 0;
        for (int x = 0; x < 128; x++) { int c = cnts[x]; cnts[x] = a; a += c; }
        cnts[128] = a;
    }
    __syncthreads();
    int total = cnts[128];
    if (total > CAP) total = CAP;

    __shared__ int   sIdx[CAP];
    __shared__ float sEx[CAP];
    __shared__ float sP[CAP];
    __shared__ float sQ[HD];
    {
        int p = cnts[t];
#pragma unroll
        for (int i = 0; i < 16; i++) {
            if (mask & (1u << i)) {
                if (p < CAP) sIdx[p] = t + i * 128;
                p++;
            }
        }
    }
    sQ[t] = g_qr[((size_t)h * SQ + row) * HD + t];
    __syncthreads();

    // --- exact fp32 rescore: sequential fmaf chain over d (bit = round1 gemm)
    for (int c = t; c < total; c += 128) {
        const float* kp = g_kr + ((size_t)kvh * SQ + sIdx[c]) * HD;
        float a = 0.f;
#pragma unroll 8
        for (int d = 0; d < HD; d++) a = fmaf(sQ[d], kp[d], a);
        sEx[c] = SCALE * a;
    }
    __syncthreads();

    // --- exact row max over candidates (global max is always a candidate)
    float m = -3.4e38f;
    for (int c = t; c < total; c += 128) m = fmaxf(m, sEx[c]);
#pragma unroll
    for (int o = 16; o > 0; o >>= 1) m = fmaxf(m, __shfl_down_sync(0xffffffffu, m, o));
    if ((t & 31) == 0) redf[t >> 5] = m;
    __syncthreads();
    float rowmax = fmaxf(fmaxf(redf[0], redf[1]), fmaxf(redf[2], redf[3]));

    // --- exact top-40 membership: kept iff #{c': sEx[c'] > sEx[c]} < TOPK or diag
    for (int c = t; c < total; c += 128) {
        float v = sEx[c];
        int cnt = 0;
        for (int c2 = 0; c2 < total; c2++) cnt += (sEx[c2] > v);
        bool kept = (cnt < TOPK) || (sIdx[c] == row);
        sP[c] = kept ? __expf(v - rowmax) : 0.f;
    }
    __syncthreads();

    // --- denominator
    float ps = 0.f;
    for (int c = t; c < total; c += 128) ps += sP[c];
#pragma unroll
    for (int o = 16; o > 0; o >>= 1) ps += __shfl_down_sync(0xffffffffu, ps, o);
    if ((t & 31) == 0) redf[t >> 5] = ps;
    __syncthreads();
    float denom = redf[0] + redf[1] + redf[2] + redf[3];

    // --- sparse PV (coalesced v rows)
    float acc = 0.f;
    for (int c = 0; c < total; c++)
        acc += sP[c] * g_v[(size_t)sIdx[c] * (NKV * HD) + kvh * HD + t];

    float o = acc / denom;
    bf16 h1 = __float2bfloat16(o);
    bf16 h2 = __float2bfloat16(o - __bfloat162float(h1));
    bf16* dst = g_at3 + (size_t)row * K3P;
    int col = h * HD + t;
    dst[col] = h1; dst[DM + col] = h1; dst[2 * DM + col] = h2;   // A-type
}

// ================= launch ====================================================
extern "C" void kernel_launch(void* const* d_in, const int* in_sizes, int n_in,
                              void* d_out, int out_size)
{
    const float* x    = (const float*)d_in[0];
    const float* cosb = (const float*)d_in[1];
    const float* sinb = (const float*)d_in[2];
    const float* Wq   = (const float*)d_in[3];
    const float* Wk   = (const float*)d_in[4];
    const float* Wv   = (const float*)d_in[5];
    const float* Wo   = (const float*)d_in[6];
    const float* qw   = (const float*)d_in[7];
    const float* kw   = (const float*)d_in[8];
    float* out = (float*)d_out;

    float *pq, *pk, *pv, *psc;
    bf16  *px3, *pwv3, *pwo3, *pqr3, *pkr3, *pat3;
    cudaGetSymbolAddress((void**)&pq,   g_q);
    cudaGetSymbolAddress((void**)&pk,   g_k);
    cudaGetSymbolAddress((void**)&pv,   g_v);
    cudaGetSymbolAddress((void**)&psc,  g_sc);
    cudaGetSymbolAddress((void**)&px3,  g_x3);
    cudaGetSymbolAddress((void**)&pwv3, g_wv3);
    cudaGetSymbolAddress((void**)&pwo3, g_wo3);
    cudaGetSymbolAddress((void**)&pqr3, g_qr3);
    cudaGetSymbolAddress((void**)&pkr3, g_kr3);
    cudaGetSymbolAddress((void**)&pat3, g_at3);

    static bool attr_done = false;
    if (!attr_done) {
        cudaFuncSetAttribute(gemm3_nt, cudaFuncAttributeMaxDynamicSharedMemorySize, GEMM_SMEM);
        attr_done = true;
    }

    // Q,K projections: fp32 SIMT, bit-identical to round-1
    gemm_nt<<<dim3(DM / 128, SQ / 128, 1), 256>>>(x, Wq, pq, SQ, DM, DM, 0, 0, 0, 1.f, 1);
    gemm_nt<<<dim3((NKV * HD) / 128, SQ / 128, 1), 256>>>(x, Wk, pk, SQ, NKV * HD, DM, 0, 0, 0, 1.f, 1);

    // bf16x3 limb conversions for the HMMA-able GEMMs
    {
        long n4;
        n4 = (long)SQ * DM / 4;
        conv3_kernel<<<(unsigned)((n4 + 255) / 256), 256>>>((const float4*)x,  px3,  n4, DM / 4, 1);
        n4 = (long)(NKV * HD) * DM / 4;
        conv3_kernel<<<(unsigned)((n4 + 255) / 256), 256>>>((const float4*)Wv, pwv3, n4, DM / 4, 0);
        n4 = (long)DM * DM / 4;
        conv3_kernel<<<(unsigned)((n4 + 255) / 256), 256>>>((const float4*)Wo, pwo3, n4, DM / 4, 0);
    }

    // V projection: bf16x3 HMMA (value-level only)
    gemm3_nt<<<dim3((NKV*HD) / 128, SQ / 128, 1), 256, GEMM_SMEM>>>(px3, pwv3, pv, NKV*HD, K3P, 0, 0, 0, 1.f, 1);

    // rms-norm + rope (fp32 outputs bit = round1; also emits bf16x3 limbs)
    rope_q_kernel<<<dim3(SQ, NH),  128>>>(cosb, sinb, qw);
    rope_k_kernel<<<dim3(SQ, NKV), 128>>>(cosb, sinb, kw);

    // approx scores: bf16x3 HMMA screening, batched over heads
    gemm3_nt<<<dim3(SQ / 128, SQ / 128, NH), 256, GEMM_SMEM>>>(
        pqr3, pkr3, psc, SQ, K3S,
        (long)SQ * K3S, (long)SQ * K3S, (long)SQ * SQ, SCALE, 2);

    // screening + exact fp32 rescore + softmax + sparse PV
    attn_select_kernel<<<dim3(SQ, NH), 128>>>();

    // O projection: bf16x3 HMMA (value-level only)
    gemm3_nt<<<dim3(DM / 128, SQ / 128, 1), 256, GEMM_SMEM>>>(pat3, pwo3, out, DM, K3P, 0, 0, 0, 1.f, 1);
}

// round 6
// speedup vs baseline: 1.4742x; 1.2685x over previous
#include <cuda_runtime.h>
#include <cuda_bf16.h>
#include <math.h>
#include <stdint.h>

typedef __nv_bfloat16 bf16;

#define SQ 2048
#define DM 2048
#define NH 16
#define NKV 8
#define HD 128
#define TOPK 40
#define SCALE 0.08838834764831845f  // 128^-0.5
#define EPS_BAND 0.05f

#define K3P (3*DM)   // 6144: triple-K (V, O projections)

// ---------------- scratch (device globals; no allocations allowed) ----------
__device__ float g_q  [(size_t)SQ * DM];          // q projection (fp32)
__device__ float g_k  [(size_t)SQ * NKV * HD];    // k projection (fp32)
__device__ float g_v  [(size_t)SQ * NKV * HD];    // v projection (HMMA)
__device__ float g_qr [(size_t)NH  * SQ * HD];    // q roped fp32 [H,S,HD]
__device__ float g_kr [(size_t)NKV * SQ * HD];    // k roped fp32 [HKV,S,HD]
__device__ float g_sc [(size_t)NH * SQ * SQ];     // approx scores (256 MB)
__device__ bf16  g_x3 [(size_t)SQ * K3P];
__device__ bf16  g_wv3[(size_t)(NKV*HD) * K3P];
__device__ bf16  g_wo3[(size_t)DM * K3P];
__device__ bf16  g_qr1[(size_t)NH  * SQ * HD];    // roped q, plain bf16 (screening)
__device__ bf16  g_kr1[(size_t)NKV * SQ * HD];    // roped k, plain bf16 (screening)
__device__ bf16  g_at3[(size_t)SQ * K3P];         // attention out, bf16x3 A-type

// ============ fp32 GEMM (round-1 proven) ====================================
__global__ __launch_bounds__(256) void gemm_nt(
    const float* __restrict__ A, const float* __restrict__ B,
    float* __restrict__ C, int M, int N, int K,
    long sA, long sB, long sC, float alpha, int bDiv)
{
    __shared__ float As[16][128];
    __shared__ float Bs[16][128];
    const float* Az = A + (long)blockIdx.z * sA;
    const float* Bz = B + (long)(blockIdx.z / bDiv) * sB;
    float*       Cz = C + (long)blockIdx.z * sC;

    int brow = blockIdx.y * 128;
    int bcol = blockIdx.x * 128;
    int tid  = threadIdx.x;
    int ty   = tid >> 4;
    int tx   = tid & 15;

    float acc[8][8];
#pragma unroll
    for (int i = 0; i < 8; i++)
#pragma unroll
        for (int j = 0; j < 8; j++) acc[i][j] = 0.f;

    for (int k0 = 0; k0 < K; k0 += 16) {
#pragma unroll
        for (int it = 0; it < 2; it++) {
            int idx = tid + it * 256;
            int r   = idx >> 2;
            int c   = (idx & 3) * 4;
            float4 va = *(const float4*)&Az[(long)(brow + r) * K + k0 + c];
            As[c + 0][r] = va.x; As[c + 1][r] = va.y;
            As[c + 2][r] = va.z; As[c + 3][r] = va.w;
            float4 vb = *(const float4*)&Bz[(long)(bcol + r) * K + k0 + c];
            Bs[c + 0][r] = vb.x; Bs[c + 1][r] = vb.y;
            Bs[c + 2][r] = vb.z; Bs[c + 3][r] = vb.w;
        }
        __syncthreads();
#pragma unroll
        for (int kk = 0; kk < 16; kk++) {
            float a[8], b[8];
#pragma unroll
            for (int i = 0; i < 8; i++) a[i] = As[kk][ty * 8 + i];
#pragma unroll
            for (int j = 0; j < 8; j++) b[j] = Bs[kk][tx * 8 + j];
#pragma unroll
            for (int i = 0; i < 8; i++)
#pragma unroll
                for (int j = 0; j < 8; j++) acc[i][j] += a[i] * b[j];
        }
        __syncthreads();
    }
#pragma unroll
    for (int i = 0; i < 8; i++) {
        long rr = brow + ty * 8 + i;
#pragma unroll
        for (int j = 0; j < 8; j++)
            Cz[rr * N + bcol + tx * 8 + j] = alpha * acc[i][j];
    }
}

// ================= HMMA helpers =============================================
__device__ __forceinline__ uint32_t smem_u32(const void* p) {
    uint32_t a;
    asm("{ .reg .u64 t; cvta.to.shared.u64 t, %1; cvt.u32.u64 %0, t; }" : "=r"(a) : "l"(p));
    return a;
}
__device__ __forceinline__ void ldmatrix_x4(uint32_t* r, uint32_t addr) {
    asm volatile("ldmatrix.sync.aligned.m8n8.x4.shared.b16 {%0,%1,%2,%3}, [%4];"
        : "=r"(r[0]), "=r"(r[1]), "=r"(r[2]), "=r"(r[3]) : "r"(addr));
}
__device__ __forceinline__ void mma16816(float* c, const uint32_t* a, const uint32_t* b) {
    asm volatile(
        "mma.sync.aligned.m16n8k16.row.col.f32.bf16.bf16.f32 "
        "{%0,%1,%2,%3}, {%4,%5,%6,%7}, {%8,%9}, {%0,%1,%2,%3};"
        : "+f"(c[0]), "+f"(c[1]), "+f"(c[2]), "+f"(c[3])
        : "r"(a[0]), "r"(a[1]), "r"(a[2]), "r"(a[3]), "r"(b[0]), "r"(b[1]));
}
__device__ __forceinline__ uint32_t sw128(uint32_t bo) { return bo ^ ((bo >> 3) & 0x70); }

// ============ bf16 GEMM-NT with cp.async 3-stage pipeline (HMMA) ============
// C[M,N] = alpha * A[M,K] @ B[N,K]^T, bf16 K-major, batched over z.
#define STAGES 3
#define STAGE_BYTES 32768u      // A tile 16KB + B tile 16KB
#define GEMM3_SMEM (STAGES * 32768 + 256)

__device__ __forceinline__ void cp_tile(uint32_t smA, uint32_t smB,
                                        const bf16* __restrict__ A, long rowA,
                                        const bf16* __restrict__ B, long rowB,
                                        int k0, int ld, int tid) {
#pragma unroll
    for (int it = 0; it < 4; it++) {
        int idx = tid + it * 256;
        int rr  = idx >> 3;
        int c16 = (idx & 7) * 16;
        uint32_t sw = sw128((uint32_t)(rr * 128 + c16));
        const void* ga = (const char*)(A + (rowA + rr) * (long)ld + k0) + c16;
        const void* gb = (const char*)(B + (rowB + rr) * (long)ld + k0) + c16;
        asm volatile("cp.async.cg.shared.global [%0], [%1], 16;" :: "r"(smA + sw), "l"(ga));
        asm volatile("cp.async.cg.shared.global [%0], [%1], 16;" :: "r"(smB + sw), "l"(gb));
    }
}

__global__ __launch_bounds__(256, 1) void gemm3_cp(
    const bf16* __restrict__ A, const bf16* __restrict__ B, float* __restrict__ C,
    int N, int K, long sA, long sB, long sC, float alpha, int bDiv)
{
    extern __shared__ char smraw[];
    uint32_t raw  = smem_u32(smraw);
    uint32_t base = (raw + 127u) & ~127u;

    const bf16* Az = A + (long)blockIdx.z * sA;
    const bf16* Bz = B + (long)(blockIdx.z / bDiv) * sB;
    float*      Cz = C + (long)blockIdx.z * sC;
    long brow = (long)blockIdx.y * 128;
    long bcol = (long)blockIdx.x * 128;
    int tid  = threadIdx.x;
    int lane = tid & 31;
    int wid  = tid >> 5;
    int wm   = wid & 3;
    int wn   = wid >> 2;

    float acc[2][8][4];
#pragma unroll
    for (int i = 0; i < 2; i++)
#pragma unroll
        for (int j = 0; j < 8; j++)
#pragma unroll
            for (int q = 0; q < 4; q++) acc[i][j][q] = 0.f;

    int NC = K / 64;

    // prologue: prefetch up to 2 chunks
    {
        int npre = NC < 2 ? NC : 2;
        for (int s = 0; s < npre; s++) {
            uint32_t st = base + (uint32_t)s * STAGE_BYTES;
            cp_tile(st, st + 16384u, Az, brow, Bz, bcol, s * 64, K, tid);
            asm volatile("cp.async.commit_group;" ::: "memory");
        }
    }

    int aRow = wm * 32 + (lane & 15);
    int aCol = (lane >> 4) * 16;
    int bRow = wn * 64 + ((lane >> 4) << 3) + (lane & 7);
    int bCol = ((lane >> 3) & 1) * 16;

    for (int c = 0; c < NC; c++) {
        if (c + 1 < NC) asm volatile("cp.async.wait_group 1;" ::: "memory");
        else            asm volatile("cp.async.wait_group 0;" ::: "memory");
        __syncthreads();

        if (c + 2 < NC) {
            uint32_t st = base + (uint32_t)((c + 2) % STAGES) * STAGE_BYTES;
            cp_tile(st, st + 16384u, Az, brow, Bz, bcol, (c + 2) * 64, K, tid);
            asm volatile("cp.async.commit_group;" ::: "memory");
        }

        uint32_t smA = base + (uint32_t)(c % STAGES) * STAGE_BYTES;
        uint32_t smB = smA + 16384u;

#pragma unroll
        for (int ks = 0; ks < 4; ks++) {
            uint32_t a[2][4];
#pragma unroll
            for (int mt = 0; mt < 2; mt++) {
                uint32_t bo = (uint32_t)((aRow + mt * 16) * 128 + aCol + ks * 32);
                ldmatrix_x4(a[mt], smA + sw128(bo));
            }
            uint32_t bb[4][4];
#pragma unroll
            for (int p = 0; p < 4; p++) {
                uint32_t bo = (uint32_t)((bRow + p * 16) * 128 + bCol + ks * 32);
                ldmatrix_x4(bb[p], smB + sw128(bo));
            }
#pragma unroll
            for (int mt = 0; mt < 2; mt++)
#pragma unroll
                for (int nt = 0; nt < 8; nt++)
                    mma16816(acc[mt][nt], a[mt], &bb[nt >> 1][(nt & 1) * 2]);
        }
        __syncthreads();
    }

    long r0 = brow + wm * 32 + (lane >> 2);
    long c0 = bcol + wn * 64 + (lane & 3) * 2;
#pragma unroll
    for (int mt = 0; mt < 2; mt++) {
#pragma unroll
        for (int nt = 0; nt < 8; nt++) {
            long rr = r0 + mt * 16;
            long cc = c0 + nt * 8;
            float2 v0 = make_float2(alpha * acc[mt][nt][0], alpha * acc[mt][nt][1]);
            float2 v1 = make_float2(alpha * acc[mt][nt][2], alpha * acc[mt][nt][3]);
            *(float2*)(Cz + rr * N + cc)       = v0;
            *(float2*)(Cz + (rr + 8) * N + cc) = v1;
        }
    }
}

// ================= fp32 -> bf16x3 limb conversion ===========================
// A-type row: [h1 | h1 | h2]    B-type row: [h1 | h2 | h1]
__global__ void conv3_kernel(const float4* __restrict__ src, bf16* __restrict__ dst,
                             long n4, int Kq, int isA)
{
    long i = (long)blockIdx.x * blockDim.x + threadIdx.x;
    if (i >= n4) return;
    long r  = i / Kq;
    int  c4 = (int)(i - r * Kq) * 4;
    int  K  = Kq * 4;
    float4 f = src[i];
    union { bf16 h[4]; uint2 u; } H1, H2;
    float fa[4] = {f.x, f.y, f.z, f.w};
#pragma unroll
    for (int j = 0; j < 4; j++) {
        H1.h[j] = __float2bfloat16(fa[j]);
        H2.h[j] = __float2bfloat16(fa[j] - __bfloat162float(H1.h[j]));
    }
    bf16* d = dst + r * (long)(3 * K) + c4;
    *(uint2*)(d)         = H1.u;
    *(uint2*)(d + K)     = isA ? H1.u : H2.u;
    *(uint2*)(d + 2 * K) = isA ? H2.u : H1.u;
}

// ================= rms-norm + rope ==========================================
__device__ __forceinline__ float blockSum128(float v, float* red) {
#pragma unroll
    for (int o = 16; o > 0; o >>= 1) v += __shfl_down_sync(0xffffffffu, v, o);
    if ((threadIdx.x & 31) == 0) red[threadIdx.x >> 5] = v;
    __syncthreads();
    return red[0] + red[1] + red[2] + red[3];
}

__global__ void rope_q_kernel(const float* __restrict__ cosb,
                              const float* __restrict__ sinb,
                              const float* __restrict__ w)
{
    int s = blockIdx.x, h = blockIdx.y, d = threadIdx.x;
    __shared__ float red[4];
    __shared__ float sh[HD];
    float v = g_q[(long)s * DM + h * HD + d];
    float ss = blockSum128(v * v, red);
    float inv = rsqrtf(ss * (1.0f / HD) + 1e-6f);
    float qn = v * inv * w[d];
    sh[d] = qn;
    __syncthreads();
    float rot = (d < 64) ? -sh[d + 64] : sh[d - 64];
    float f = qn * cosb[s * HD + d] + rot * sinb[s * HD + d];
    g_qr [((size_t)h * SQ + s) * HD + d] = f;
    g_qr1[((size_t)h * SQ + s) * HD + d] = __float2bfloat16(f);
}

__global__ void rope_k_kernel(const float* __restrict__ cosb,
                              const float* __restrict__ sinb,
                              const float* __restrict__ w)
{
    int s = blockIdx.x, h = blockIdx.y, d = threadIdx.x;
    __shared__ float red[4];
    __shared__ float sh[HD];
    float v = g_k[(long)s * (NKV * HD) + h * HD + d];
    float ss = blockSum128(v * v, red);
    float inv = rsqrtf(ss * (1.0f / HD) + 1e-6f);
    float kn = v * inv * w[d];
    sh[d] = kn;
    __syncthreads();
    float rot = (d < 64) ? -sh[d + 64] : sh[d - 64];
    float f = kn * cosb[s * HD + d] + rot * sinb[s * HD + d];
    g_kr [((size_t)h * SQ + s) * HD + d] = f;
    g_kr1[((size_t)h * SQ + s) * HD + d] = __float2bfloat16(f);
}

// ================= screening + exact rescore + softmax + sparse PV ==========
__device__ __forceinline__ unsigned fkey(float f) {
    unsigned u = __float_as_uint(f);
    return (u & 0x80000000u) ? ~u : (u | 0x80000000u);
}
__device__ __forceinline__ float unfkey(unsigned u) {
    unsigned v = (u & 0x80000000u) ? (u & 0x7FFFFFFFu) : ~u;
    return __uint_as_float(v);
}

#define CAP 256

__global__ void attn_select_kernel()
{
    int row = blockIdx.x, h = blockIdx.y;
    int kvh = h >> 1;
    int t = threadIdx.x;
    int lane = t & 31;
    int wid  = t >> 5;
    const float* srow = g_sc + ((size_t)h * SQ + row) * SQ;

    float    val[16];
    unsigned key[16];
#pragma unroll
    for (int i = 0; i < 16; i++) {
        float v = srow[t + i * 128];
        val[i] = v;
        key[i] = fkey(v);
    }

    __shared__ float redf[4];
    __shared__ int   redc[4];

    // approx 40th-largest (binary search on monotone uint keys)
    unsigned lo = 0u, hi = 0xFFFFFFFFu;
    while (lo < hi) {
        unsigned mid = lo + ((hi - lo) >> 1) + 1u;
        int c = 0;
#pragma unroll
        for (int i = 0; i < 16; i++) c += (key[i] >= mid);
#pragma unroll
        for (int o = 16; o > 0; o >>= 1) c += __shfl_down_sync(0xffffffffu, c, o);
        __syncthreads();
        if ((t & 31) == 0) redc[t >> 5] = c;
        __syncthreads();
        int cnt = redc[0] + redc[1] + redc[2] + redc[3];
        if (cnt >= TOPK) lo = mid; else hi = mid - 1u;
    }
    float band = unfkey(lo) - EPS_BAND;

    // band mask + deterministic compaction
    unsigned mask = 0;
#pragma unroll
    for (int i = 0; i < 16; i++) {
        int j = t + i * 128;
        if (val[i] >= band || j == row) mask |= (1u << i);
    }
    int mc = __popc(mask);

    __shared__ int cnts[129];
    cnts[t] = mc;
    __syncthreads();
    if (t == 0) {
        int a = 0;
        for (int x = 0; x < 128; x++) { int c = cnts[x]; cnts[x] = a; a += c; }
        cnts[128] = a;
    }
    __syncthreads();
    int total = cnts[128];
    if (total > CAP) total = CAP;

    __shared__ int   sIdx[CAP];
    __shared__ float sEx[CAP];
    __shared__ float sP[CAP];
    __shared__ float sQ[HD];
    {
        int p = cnts[t];
#pragma unroll
        for (int i = 0; i < 16; i++) {
            if (mask & (1u << i)) {
                if (p < CAP) sIdx[p] = t + i * 128;
                p++;
            }
        }
    }
    sQ[t] = g_qr[((size_t)h * SQ + row) * HD + t];
    __syncthreads();

    // exact fp32 rescore: warp-cooperative (coalesced k-row loads)
    for (int c = wid; c < total; c += 4) {
        const float* kp = g_kr + ((size_t)kvh * SQ + sIdx[c]) * HD;
        float part = 0.f;
#pragma unroll
        for (int d = lane; d < HD; d += 32) part = fmaf(sQ[d], kp[d], part);
#pragma unroll
        for (int o = 16; o > 0; o >>= 1) part += __shfl_down_sync(0xffffffffu, part, o);
        if (lane == 0) sEx[c] = SCALE * part;
    }
    __syncthreads();

    // exact row max over candidates
    float m = -3.4e38f;
    for (int c = t; c < total; c += 128) m = fmaxf(m, sEx[c]);
#pragma unroll
    for (int o = 16; o > 0; o >>= 1) m = fmaxf(m, __shfl_down_sync(0xffffffffu, m, o));
    if ((t & 31) == 0) redf[t >> 5] = m;
    __syncthreads();
    float rowmax = fmaxf(fmaxf(redf[0], redf[1]), fmaxf(redf[2], redf[3]));

    // exact top-40 membership among candidates
    for (int c = t; c < total; c += 128) {
        float v = sEx[c];
        int cnt = 0;
        for (int c2 = 0; c2 < total; c2++) cnt += (sEx[c2] > v);
        bool kept = (cnt < TOPK) || (sIdx[c] == row);
        sP[c] = kept ? __expf(v - rowmax) : 0.f;
    }
    __syncthreads();

    // denominator
    float ps = 0.f;
    for (int c = t; c < total; c += 128) ps += sP[c];
#pragma unroll
    for (int o = 16; o > 0; o >>= 1) ps += __shfl_down_sync(0xffffffffu, ps, o);
    if ((t & 31) == 0) redf[t >> 5] = ps;
    __syncthreads();
    float denom = redf[0] + redf[1] + redf[2] + redf[3];

    // sparse PV (coalesced v rows)
    float acc = 0.f;
    for (int c = 0; c < total; c++)
        acc += sP[c] * g_v[(size_t)sIdx[c] * (NKV * HD) + kvh * HD + t];

    float o = acc / denom;
    bf16 h1 = __float2bfloat16(o);
    bf16 h2 = __float2bfloat16(o - __bfloat162float(h1));
    bf16* dst = g_at3 + (size_t)row * K3P;
    int col = h * HD + t;
    dst[col] = h1; dst[DM + col] = h1; dst[2 * DM + col] = h2;   // A-type
}

// ================= launch ====================================================
extern "C" void kernel_launch(void* const* d_in, const int* in_sizes, int n_in,
                              void* d_out, int out_size)
{
    const float* x    = (const float*)d_in[0];
    const float* cosb = (const float*)d_in[1];
    const float* sinb = (const float*)d_in[2];
    const float* Wq   = (const float*)d_in[3];
    const float* Wk   = (const float*)d_in[4];
    const float* Wv   = (const float*)d_in[5];
    const float* Wo   = (const float*)d_in[6];
    const float* qw   = (const float*)d_in[7];
    const float* kw   = (const float*)d_in[8];
    float* out = (float*)d_out;

    float *pq, *pk, *pv, *psc;
    bf16  *px3, *pwv3, *pwo3, *pqr1, *pkr1, *pat3;
    cudaGetSymbolAddress((void**)&pq,   g_q);
    cudaGetSymbolAddress((void**)&pk,   g_k);
    cudaGetSymbolAddress((void**)&pv,   g_v);
    cudaGetSymbolAddress((void**)&psc,  g_sc);
    cudaGetSymbolAddress((void**)&px3,  g_x3);
    cudaGetSymbolAddress((void**)&pwv3, g_wv3);
    cudaGetSymbolAddress((void**)&pwo3, g_wo3);
    cudaGetSymbolAddress((void**)&pqr1, g_qr1);
    cudaGetSymbolAddress((void**)&pkr1, g_kr1);
    cudaGetSymbolAddress((void**)&pat3, g_at3);

    static bool attr_done = false;
    if (!attr_done) {
        cudaFuncSetAttribute(gemm3_cp, cudaFuncAttributeMaxDynamicSharedMemorySize, GEMM3_SMEM);
        attr_done = true;
    }

    // Q,K projections: fp32 SIMT (selection-critical inputs)
    gemm_nt<<<dim3(DM / 128, SQ / 128, 1), 256>>>(x, Wq, pq, SQ, DM, DM, 0, 0, 0, 1.f, 1);
    gemm_nt<<<dim3((NKV * HD) / 128, SQ / 128, 1), 256>>>(x, Wk, pk, SQ, NKV * HD, DM, 0, 0, 0, 1.f, 1);

    // bf16x3 limb conversions (V, O operands)
    {
        long n4;
        n4 = (long)SQ * DM / 4;
        conv3_kernel<<<(unsigned)((n4 + 255) / 256), 256>>>((const float4*)x,  px3,  n4, DM / 4, 1);
        n4 = (long)(NKV * HD) * DM / 4;
        conv3_kernel<<<(unsigned)((n4 + 255) / 256), 256>>>((const float4*)Wv, pwv3, n4, DM / 4, 0);
        n4 = (long)DM * DM / 4;
        conv3_kernel<<<(unsigned)((n4 + 255) / 256), 256>>>((const float4*)Wo, pwo3, n4, DM / 4, 0);
    }

    // V projection: bf16x3 HMMA
    gemm3_cp<<<dim3((NKV*HD) / 128, SQ / 128, 1), 256, GEMM3_SMEM>>>(px3, pwv3, pv, NKV*HD, K3P, 0, 0, 0, 1.f, 1);

    // rms-norm + rope (fp32 + plain-bf16 screening copies)
    rope_q_kernel<<<dim3(SQ, NH),  128>>>(cosb, sinb, qw);
    rope_k_kernel<<<dim3(SQ, NKV), 128>>>(cosb, sinb, kw);

    // screening scores: plain bf16, K=128, batched over heads
    gemm3_cp<<<dim3(SQ / 128, SQ / 128, NH), 256, GEMM3_SMEM>>>(
        pqr1, pkr1, psc, SQ, HD,
        (long)SQ * HD, (long)SQ * HD, (long)SQ * SQ, SCALE, 2);

    // screening + exact fp32 rescore + softmax + sparse PV
    attn_select_kernel<<<dim3(SQ, NH), 128>>>();

    // O projection: bf16x3 HMMA
    gemm3_cp<<<dim3(DM / 128, SQ / 128, 1), 256, GEMM3_SMEM>>>(pat3, pwo3, out, DM, K3P, 0, 0, 0, 1.f, 1);
}

// round 9
// speedup vs baseline: 1.7201x; 1.1668x over previous
#include <cuda_runtime.h>
#include <cuda_bf16.h>
#include <math.h>
#include <stdint.h>

typedef __nv_bfloat16 bf16;

#define SQ 2048
#define DM 2048
#define NH 16
#define NKV 8
#define HD 128
#define KN (NKV*HD)          // 1024
#define TOPK 40
#define SCALE 0.08838834764831845f  // 128^-0.5
#define EPS_BAND 0.06f

#define K3P (3*DM)           // 6144: triple-K (V, O projections)

// ---------------- scratch (device globals; no allocations allowed) ----------
__device__ float g_qp [(size_t)2 * SQ * DM];      // Q projection K-split partials
__device__ float g_kp [(size_t)2 * SQ * KN];      // K projection K-split partials
__device__ float g_q  [(size_t)SQ * DM];
__device__ float g_k  [(size_t)SQ * KN];
__device__ float g_v  [(size_t)SQ * KN];
__device__ float g_qr [(size_t)NH  * SQ * HD];
__device__ float g_kr [(size_t)NKV * SQ * HD];
__device__ bf16  g_scb[(size_t)NH * SQ * SQ];     // screening scores, bf16 (128 MB)
__device__ bf16  g_x3 [(size_t)SQ * K3P];
__device__ bf16  g_wv3[(size_t)KN * K3P];
__device__ bf16  g_wo3[(size_t)DM * K3P];
__device__ bf16  g_qr1[(size_t)NH  * SQ * HD];
__device__ bf16  g_kr1[(size_t)NKV * SQ * HD];
__device__ bf16  g_at3[(size_t)SQ * K3P];

// ============ fused Q+K fp32 projection, K-split x2 (wave-packed) ===========
// grid (24, 16, 2): x<16 -> Q tile, else K tile; z = K half. Inner loop is the
// round-1-proven SIMT GEMM body (fp32-class accumulation for selection path).
__global__ __launch_bounds__(256) void qk_gemm(
    const float* __restrict__ x, const float* __restrict__ Wq,
    const float* __restrict__ Wk)
{
    __shared__ float As[16][128];
    __shared__ float Bs[16][128];

    int bx = blockIdx.x;
    bool isQ = bx < 16;
    int bcol = (isQ ? bx : bx - 16) * 128;
    const float* B = isQ ? Wq : Wk;
    int N = isQ ? DM : KN;
    float* C = isQ ? (g_qp + (size_t)blockIdx.z * SQ * DM)
                   : (g_kp + (size_t)blockIdx.z * SQ * KN);
    int brow = blockIdx.y * 128;
    int kbeg = blockIdx.z * 1024;

    int tid = threadIdx.x;
    int ty  = tid >> 4;
    int tx  = tid & 15;

    float acc[8][8];
#pragma unroll
    for (int i = 0; i < 8; i++)
#pragma unroll
        for (int j = 0; j < 8; j++) acc[i][j] = 0.f;

    for (int k0 = kbeg; k0 < kbeg + 1024; k0 += 16) {
#pragma unroll
        for (int it = 0; it < 2; it++) {
            int idx = tid + it * 256;
            int r   = idx >> 2;
            int c   = (idx & 3) * 4;
            float4 va = *(const float4*)&x[(long)(brow + r) * DM + k0 + c];
            As[c + 0][r] = va.x; As[c + 1][r] = va.y;
            As[c + 2][r] = va.z; As[c + 3][r] = va.w;
            float4 vb = *(const float4*)&B[(long)(bcol + r) * DM + k0 + c];
            Bs[c + 0][r] = vb.x; Bs[c + 1][r] = vb.y;
            Bs[c + 2][r] = vb.z; Bs[c + 3][r] = vb.w;
        }
        __syncthreads();
#pragma unroll
        for (int kk = 0; kk < 16; kk++) {
            float a[8], b[8];
#pragma unroll
            for (int i = 0; i < 8; i++) a[i] = As[kk][ty * 8 + i];
#pragma unroll
            for (int j = 0; j < 8; j++) b[j] = Bs[kk][tx * 8 + j];
#pragma unroll
            for (int i = 0; i < 8; i++)
#pragma unroll
                for (int j = 0; j < 8; j++) acc[i][j] += a[i] * b[j];
        }
        __syncthreads();
    }
#pragma unroll
    for (int i = 0; i < 8; i++) {
        long rr = brow + ty * 8 + i;
#pragma unroll
        for (int j = 0; j < 8; j++)
            C[rr * N + bcol + tx * 8 + j] = acc[i][j];
    }
}

// combine K-split partials (deterministic elementwise add)
__global__ void add_halves(const float4* __restrict__ a, const float4* __restrict__ b,
                           float4* __restrict__ c, long n4)
{
    long i = (long)blockIdx.x * blockDim.x + threadIdx.x;
    if (i >= n4) return;
    float4 u = a[i], v = b[i];
    c[i] = make_float4(u.x + v.x, u.y + v.y, u.z + v.z, u.w + v.w);
}

// ================= HMMA helpers =============================================
__device__ __forceinline__ uint32_t smem_u32(const void* p) {
    uint32_t a;
    asm("{ .reg .u64 t; cvta.to.shared.u64 t, %1; cvt.u32.u64 %0, t; }" : "=r"(a) : "l"(p));
    return a;
}
__device__ __forceinline__ void ldmatrix_x4(uint32_t* r, uint32_t addr) {
    asm volatile("ldmatrix.sync.aligned.m8n8.x4.shared.b16 {%0,%1,%2,%3}, [%4];"
        : "=r"(r[0]), "=r"(r[1]), "=r"(r[2]), "=r"(r[3]) : "r"(addr));
}
__device__ __forceinline__ void mma16816(float* c, const uint32_t* a, const uint32_t* b) {
    asm volatile(
        "mma.sync.aligned.m16n8k16.row.col.f32.bf16.bf16.f32 "
        "{%0,%1,%2,%3}, {%4,%5,%6,%7}, {%8,%9}, {%0,%1,%2,%3};"
        : "+f"(c[0]), "+f"(c[1]), "+f"(c[2]), "+f"(c[3])
        : "r"(a[0]), "r"(a[1]), "r"(a[2]), "r"(a[3]), "r"(b[0]), "r"(b[1]));
}
__device__ __forceinline__ uint32_t sw128(uint32_t bo) { return bo ^ ((bo >> 3) & 0x70); }

// ============ bf16 GEMM-NT with cp.async 3-stage pipeline (HMMA) ============
#define STAGES 3
#define STAGE_BYTES 32768u
#define GEMM3_SMEM (STAGES * 32768 + 256)

__device__ __forceinline__ void cp_tile(uint32_t smA, uint32_t smB,
                                        const bf16* __restrict__ A, long rowA,
                                        const bf16* __restrict__ B, long rowB,
                                        int k0, int ld, int tid) {
#pragma unroll
    for (int it = 0; it < 4; it++) {
        int idx = tid + it * 256;
        int rr  = idx >> 3;
        int c16 = (idx & 7) * 16;
        uint32_t sw = sw128((uint32_t)(rr * 128 + c16));
        const void* ga = (const char*)(A + (rowA + rr) * (long)ld + k0) + c16;
        const void* gb = (const char*)(B + (rowB + rr) * (long)ld + k0) + c16;
        asm volatile("cp.async.cg.shared.global [%0], [%1], 16;" :: "r"(smA + sw), "l"(ga));
        asm volatile("cp.async.cg.shared.global [%0], [%1], 16;" :: "r"(smB + sw), "l"(gb));
    }
}

// shared mainloop; FP16OUT=0 -> fp32 C, FP16OUT=1 -> bf16 C
template <int BFOUT>
__device__ __forceinline__ void gemm3_body(
    const bf16* __restrict__ Az, const bf16* __restrict__ Bz,
    float* Cz, bf16* Czb, int N, int K, float alpha)
{
    extern __shared__ char smraw[];
    uint32_t raw  = smem_u32(smraw);
    uint32_t base = (raw + 127u) & ~127u;

    long brow = (long)blockIdx.y * 128;
    long bcol = (long)blockIdx.x * 128;
    int tid  = threadIdx.x;
    int lane = tid & 31;
    int wid  = tid >> 5;
    int wm   = wid & 3;
    int wn   = wid >> 2;

    float acc[2][8][4];
#pragma unroll
    for (int i = 0; i < 2; i++)
#pragma unroll
        for (int j = 0; j < 8; j++)
#pragma unroll
            for (int q = 0; q < 4; q++) acc[i][j][q] = 0.f;

    int NC = K / 64;
    {
        int npre = NC < 2 ? NC : 2;
        for (int s = 0; s < npre; s++) {
            uint32_t st = base + (uint32_t)s * STAGE_BYTES;
            cp_tile(st, st + 16384u, Az, brow, Bz, bcol, s * 64, K, tid);
            asm volatile("cp.async.commit_group;" ::: "memory");
        }
    }

    int aRow = wm * 32 + (lane & 15);
    int aCol = (lane >> 4) * 16;
    int bRow = wn * 64 + ((lane >> 4) << 3) + (lane & 7);
    int bCol = ((lane >> 3) & 1) * 16;

    for (int c = 0; c < NC; c++) {
        if (c + 1 < NC) asm volatile("cp.async.wait_group 1;" ::: "memory");
        else            asm volatile("cp.async.wait_group 0;" ::: "memory");
        __syncthreads();

        if (c + 2 < NC) {
            uint32_t st = base + (uint32_t)((c + 2) % STAGES) * STAGE_BYTES;
            cp_tile(st, st + 16384u, Az, brow, Bz, bcol, (c + 2) * 64, K, tid);
            asm volatile("cp.async.commit_group;" ::: "memory");
        }

        uint32_t smA = base + (uint32_t)(c % STAGES) * STAGE_BYTES;
        uint32_t smB = smA + 16384u;

#pragma unroll
        for (int ks = 0; ks < 4; ks++) {
            uint32_t a[2][4];
#pragma unroll
            for (int mt = 0; mt < 2; mt++) {
                uint32_t bo = (uint32_t)((aRow + mt * 16) * 128 + aCol + ks * 32);
                ldmatrix_x4(a[mt], smA + sw128(bo));
            }
            uint32_t bb[4][4];
#pragma unroll
            for (int p = 0; p < 4; p++) {
                uint32_t bo = (uint32_t)((bRow + p * 16) * 128 + bCol + ks * 32);
                ldmatrix_x4(bb[p], smB + sw128(bo));
            }
#pragma unroll
            for (int mt = 0; mt < 2; mt++)
#pragma unroll
                for (int nt = 0; nt < 8; nt++)
                    mma16816(acc[mt][nt], a[mt], &bb[nt >> 1][(nt & 1) * 2]);
        }
        __syncthreads();
    }

    long r0 = brow + wm * 32 + (lane >> 2);
    long c0 = bcol + wn * 64 + (lane & 3) * 2;
#pragma unroll
    for (int mt = 0; mt < 2; mt++) {
#pragma unroll
        for (int nt = 0; nt < 8; nt++) {
            long rr = r0 + mt * 16;
            long cc = c0 + nt * 8;
            if (BFOUT) {
                __nv_bfloat162 v0 = __floats2bfloat162_rn(alpha * acc[mt][nt][0], alpha * acc[mt][nt][1]);
                __nv_bfloat162 v1 = __floats2bfloat162_rn(alpha * acc[mt][nt][2], alpha * acc[mt][nt][3]);
                *(__nv_bfloat162*)(Czb + rr * N + cc)       = v0;
                *(__nv_bfloat162*)(Czb + (rr + 8) * N + cc) = v1;
            } else {
                float2 v0 = make_float2(alpha * acc[mt][nt][0], alpha * acc[mt][nt][1]);
                float2 v1 = make_float2(alpha * acc[mt][nt][2], alpha * acc[mt][nt][3]);
                *(float2*)(Cz + rr * N + cc)       = v0;
                *(float2*)(Cz + (rr + 8) * N + cc) = v1;
            }
        }
    }
}

__global__ __launch_bounds__(256, 1) void gemm3_cp(
    const bf16* __restrict__ A, const bf16* __restrict__ B, float* __restrict__ C,
    int N, int K, long sA, long sB, long sC, float alpha, int bDiv)
{
    const bf16* Az = A + (long)blockIdx.z * sA;
    const bf16* Bz = B + (long)(blockIdx.z / bDiv) * sB;
    float*      Cz = C + (long)blockIdx.z * sC;
    gemm3_body<0>(Az, Bz, Cz, nullptr, N, K, alpha);
}

__global__ __launch_bounds__(256, 1) void gemm3_cp_bf(
    const bf16* __restrict__ A, const bf16* __restrict__ B, bf16* __restrict__ C,
    int N, int K, long sA, long sB, long sC, float alpha, int bDiv)
{
    const bf16* Az = A + (long)blockIdx.z * sA;
    const bf16* Bz = B + (long)(blockIdx.z / bDiv) * sB;
    bf16*       Cz = C + (long)blockIdx.z * sC;
    gemm3_body<1>(Az, Bz, nullptr, Cz, N, K, alpha);
}

// ================= fp32 -> bf16x3 limb conversion ===========================
// A-type row: [h1 | h1 | h2]    B-type row: [h1 | h2 | h1]
__global__ void conv3_kernel(const float4* __restrict__ src, bf16* __restrict__ dst,
                             long n4, int Kq, int isA)
{
    long i = (long)blockIdx.x * blockDim.x + threadIdx.x;
    if (i >= n4) return;
    long r  = i / Kq;
    int  c4 = (int)(i - r * Kq) * 4;
    int  K  = Kq * 4;
    float4 f = src[i];
    union { bf16 h[4]; uint2 u; } H1, H2;
    float fa[4] = {f.x, f.y, f.z, f.w};
#pragma unroll
    for (int j = 0; j < 4; j++) {
        H1.h[j] = __float2bfloat16(fa[j]);
        H2.h[j] = __float2bfloat16(fa[j] - __bfloat162float(H1.h[j]));
    }
    bf16* d = dst + r * (long)(3 * K) + c4;
    *(uint2*)(d)         = H1.u;
    *(uint2*)(d + K)     = isA ? H1.u : H2.u;
    *(uint2*)(d + 2 * K) = isA ? H2.u : H1.u;
}

// ================= rms-norm + rope ==========================================
__device__ __forceinline__ float blockSum128(float v, float* red) {
#pragma unroll
    for (int o = 16; o > 0; o >>= 1) v += __shfl_down_sync(0xffffffffu, v, o);
    if ((threadIdx.x & 31) == 0) red[threadIdx.x >> 5] = v;
    __syncthreads();
    return red[0] + red[1] + red[2] + red[3];
}

__global__ void rope_q_kernel(const float* __restrict__ cosb,
                              const float* __restrict__ sinb,
                              const float* __restrict__ w)
{
    int s = blockIdx.x, h = blockIdx.y, d = threadIdx.x;
    __shared__ float red[4];
    __shared__ float sh[HD];
    float v = g_q[(long)s * DM + h * HD + d];
    float ss = blockSum128(v * v, red);
    float inv = rsqrtf(ss * (1.0f / HD) + 1e-6f);
    float qn = v * inv * w[d];
    sh[d] = qn;
    __syncthreads();
    float rot = (d < 64) ? -sh[d + 64] : sh[d - 64];
    float f = qn * cosb[s * HD + d] + rot * sinb[s * HD + d];
    g_qr [((size_t)h * SQ + s) * HD + d] = f;
    g_qr1[((size_t)h * SQ + s) * HD + d] = __float2bfloat16(f);
}

__global__ void rope_k_kernel(const float* __restrict__ cosb,
                              const float* __restrict__ sinb,
                              const float* __restrict__ w)
{
    int s = blockIdx.x, h = blockIdx.y, d = threadIdx.x;
    __shared__ float red[4];
    __shared__ float sh[HD];
    float v = g_k[(long)s * KN + h * HD + d];
    float ss = blockSum128(v * v, red);
    float inv = rsqrtf(ss * (1.0f / HD) + 1e-6f);
    float kn = v * inv * w[d];
    sh[d] = kn;
    __syncthreads();
    float rot = (d < 64) ? -sh[d + 64] : sh[d - 64];
    float f = kn * cosb[s * HD + d] + rot * sinb[s * HD + d];
    g_kr [((size_t)h * SQ + s) * HD + d] = f;
    g_kr1[((size_t)h * SQ + s) * HD + d] = __float2bfloat16(f);
}

// ================= screening + exact rescore + softmax + sparse PV ==========
__device__ __forceinline__ unsigned fkey(float f) {
    unsigned u = __float_as_uint(f);
    return (u & 0x80000000u) ? ~u : (u | 0x80000000u);
}
__device__ __forceinline__ float unfkey(unsigned u) {
    unsigned v = (u & 0x80000000u) ? (u & 0x7FFFFFFFu) : ~u;
    return __uint_as_float(v);
}

#define CAP 320

__global__ void attn_select_kernel()
{
    int row = blockIdx.x, h = blockIdx.y;
    int kvh = h >> 1;
    int t = threadIdx.x;
    int lane = t & 31;
    int wid  = t >> 5;
    const uint4* srow = (const uint4*)(g_scb + ((size_t)h * SQ + row) * SQ);

    // 16 bf16 scores per thread via 2 x uint4 (8 bf16 each)
    float    val[16];
    unsigned key[16];
#pragma unroll
    for (int i = 0; i < 2; i++) {
        uint4 u = srow[t + i * 128];
        unsigned ws[4] = {u.x, u.y, u.z, u.w};
#pragma unroll
        for (int wq = 0; wq < 4; wq++) {
            float lo = __bfloat162float(__ushort_as_bfloat16((unsigned short)(ws[wq] & 0xFFFFu)));
            float hi = __bfloat162float(__ushort_as_bfloat16((unsigned short)(ws[wq] >> 16)));
            int j = i * 8 + wq * 2;
            val[j] = lo;     key[j]     = fkey(lo);
            val[j + 1] = hi; key[j + 1] = fkey(hi);
        }
    }

    __shared__ float redf[4];
    __shared__ int   redc[2][4];

    // approx threshold key: prefix binary search over top 16 bits only.
    // quantization only LOWERS the threshold -> superset of candidates.
    unsigned thrKey = 0u;
#pragma unroll
    for (int b = 31; b >= 16; b--) {
        unsigned cand = thrKey | (1u << b);
        int c = 0;
#pragma unroll
        for (int i = 0; i < 16; i++) c += (key[i] >= cand);
        c = __reduce_add_sync(0xffffffffu, c);
        int buf = b & 1;
        if (lane == 0) redc[buf][wid] = c;
        __syncthreads();
        int cnt = redc[buf][0] + redc[buf][1] + redc[buf][2] + redc[buf][3];
        if (cnt >= TOPK) thrKey = cand;
    }
    float band = unfkey(thrKey) - EPS_BAND;

    // band mask + deterministic compaction; col of val[j] = 8*(t + (j>>3)*128) + (j&7)
    unsigned mask = 0;
#pragma unroll
    for (int i = 0; i < 16; i++) {
        int col = 8 * (t + (i >> 3) * 128) + (i & 7);
        if (val[i] >= band || col == row) mask |= (1u << i);
    }
    int mc = __popc(mask);

    __shared__ int cnts[129];
    cnts[t] = mc;
    __syncthreads();
    if (t == 0) {
        int a = 0;
        for (int x = 0; x < 128; x++) { int c = cnts[x]; cnts[x] = a; a += c; }
        cnts[128] = a;
    }
    __syncthreads();
    int total = cnts[128];
    if (total > CAP) total = CAP;

    __shared__ int    sIdx[CAP];
    __shared__ float  sEx[CAP];
    __shared__ float  sP[CAP];
    __shared__ float4 sQ4[32];
    {
        int p = cnts[t];
#pragma unroll
        for (int i = 0; i < 16; i++) {
            if (mask & (1u << i)) {
                if (p < CAP) sIdx[p] = 8 * (t + (i >> 3) * 128) + (i & 7);
                p++;
            }
        }
    }
    if (t < 32) sQ4[t] = ((const float4*)(g_qr + ((size_t)h * SQ + row) * HD))[t];
    __syncthreads();

    // exact fp32 rescore: one warp per candidate, float4 coalesced loads
    for (int c = wid; c < total; c += 4) {
        const float4* kp = (const float4*)(g_kr + ((size_t)kvh * SQ + sIdx[c]) * HD);
        float4 k4 = kp[lane];
        float4 q4 = sQ4[lane];
        float part = q4.x * k4.x;
        part = fmaf(q4.y, k4.y, part);
        part = fmaf(q4.z, k4.z, part);
        part = fmaf(q4.w, k4.w, part);
#pragma unroll
        for (int o = 16; o > 0; o >>= 1) part += __shfl_down_sync(0xffffffffu, part, o);
        if (lane == 0) sEx[c] = SCALE * part;
    }
    __syncthreads();

    // exact row max over candidates
    float m = -3.4e38f;
    for (int c = t; c < total; c += 128) m = fmaxf(m, sEx[c]);
#pragma unroll
    for (int o = 16; o > 0; o >>= 1) m = fmaxf(m, __shfl_down_sync(0xffffffffu, m, o));
    if (lane == 0) redf[wid] = m;
    __syncthreads();
    float rowmax = fmaxf(fmaxf(redf[0], redf[1]), fmaxf(redf[2], redf[3]));

    // exact top-40 membership among candidates
    for (int c = t; c < total; c += 128) {
        float v = sEx[c];
        int cnt = 0;
        for (int c2 = 0; c2 < total; c2++) cnt += (sEx[c2] > v);
        bool kept = (cnt < TOPK) || (sIdx[c] == row);
        sP[c] = kept ? __expf(v - rowmax) : 0.f;
    }
    __syncthreads();

    // denominator
    float ps = 0.f;
    for (int c = t; c < total; c += 128) ps += sP[c];
#pragma unroll
    for (int o = 16; o > 0; o >>= 1) ps += __shfl_down_sync(0xffffffffu, ps, o);
    if (lane == 0) redf[wid] = ps;
    __syncthreads();
    float denom = redf[0] + redf[1] + redf[2] + redf[3];

    // sparse PV (coalesced v rows)
    float acc = 0.f;
    for (int c = 0; c < total; c++)
        acc += sP[c] * g_v[(size_t)sIdx[c] * KN + kvh * HD + t];

    float o = acc / denom;
    bf16 h1 = __float2bfloat16(o);
    bf16 h2 = __float2bfloat16(o - __bfloat162float(h1));
    bf16* dst = g_at3 + (size_t)row * K3P;
    int col = h * HD + t;
    dst[col] = h1; dst[DM + col] = h1; dst[2 * DM + col] = h2;   // A-type
}

// ================= launch (single stream — linear graph) =====================
extern "C" void kernel_launch(void* const* d_in, const int* in_sizes, int n_in,
                              void* d_out, int out_size)
{
    const float* x    = (const float*)d_in[0];
    const float* cosb = (const float*)d_in[1];
    const float* sinb = (const float*)d_in[2];
    const float* Wq   = (const float*)d_in[3];
    const float* Wk   = (const float*)d_in[4];
    const float* Wv   = (const float*)d_in[5];
    const float* Wo   = (const float*)d_in[6];
    const float* qw   = (const float*)d_in[7];
    const float* kw   = (const float*)d_in[8];
    float* out = (float*)d_out;

    float *pq, *pk, *pv, *pqp, *pkp;
    bf16  *pscb, *px3, *pwv3, *pwo3, *pqr1, *pkr1, *pat3;
    cudaGetSymbolAddress((void**)&pq,   g_q);
    cudaGetSymbolAddress((void**)&pk,   g_k);
    cudaGetSymbolAddress((void**)&pv,   g_v);
    cudaGetSymbolAddress((void**)&pqp,  g_qp);
    cudaGetSymbolAddress((void**)&pkp,  g_kp);
    cudaGetSymbolAddress((void**)&pscb, g_scb);
    cudaGetSymbolAddress((void**)&px3,  g_x3);
    cudaGetSymbolAddress((void**)&pwv3, g_wv3);
    cudaGetSymbolAddress((void**)&pwo3, g_wo3);
    cudaGetSymbolAddress((void**)&pqr1, g_qr1);
    cudaGetSymbolAddress((void**)&pkr1, g_kr1);
    cudaGetSymbolAddress((void**)&pat3, g_at3);

    static bool attr_done = false;
    if (!attr_done) {
        cudaFuncSetAttribute(gemm3_cp,    cudaFuncAttributeMaxDynamicSharedMemorySize, GEMM3_SMEM);
        cudaFuncSetAttribute(gemm3_cp_bf, cudaFuncAttributeMaxDynamicSharedMemorySize, GEMM3_SMEM);
        attr_done = true;
    }

    // limb conversions (x, Wv, Wo)
    {
        long n4;
        n4 = (long)SQ * DM / 4;
        conv3_kernel<<<(unsigned)((n4 + 255) / 256), 256>>>((const float4*)x,  px3,  n4, DM / 4, 1);
        n4 = (long)KN * DM / 4;
        conv3_kernel<<<(unsigned)((n4 + 255) / 256), 256>>>((const float4*)Wv, pwv3, n4, DM / 4, 0);
        n4 = (long)DM * DM / 4;
        conv3_kernel<<<(unsigned)((n4 + 255) / 256), 256>>>((const float4*)Wo, pwo3, n4, DM / 4, 0);
    }

    // fused Q+K fp32 projection, K-split x2, then deterministic combine
    qk_gemm<<<dim3(24, 16, 2), 256>>>(x, Wq, Wk);
    {
        long n4q = (long)SQ * DM / 4;
        add_halves<<<(unsigned)((n4q + 255) / 256), 256>>>(
            (const float4*)pqp, (const float4*)(pqp + (size_t)SQ * DM), (float4*)pq, n4q);
        long n4k = (long)SQ * KN / 4;
        add_halves<<<(unsigned)((n4k + 255) / 256), 256>>>(
            (const float4*)pkp, (const float4*)(pkp + (size_t)SQ * KN), (float4*)pk, n4k);
    }

    // V projection: bf16x3 HMMA
    gemm3_cp<<<dim3(KN / 128, SQ / 128, 1), 256, GEMM3_SMEM>>>(px3, pwv3, pv, KN, K3P, 0, 0, 0, 1.f, 1);

    // rms-norm + rope (fp32 + plain-bf16 screening copies)
    rope_q_kernel<<<dim3(SQ, NH),  128>>>(cosb, sinb, qw);
    rope_k_kernel<<<dim3(SQ, NKV), 128>>>(cosb, sinb, kw);

    // screening scores: plain bf16 inputs AND bf16 output buffer (halved traffic)
    gemm3_cp_bf<<<dim3(SQ / 128, SQ / 128, NH), 256, GEMM3_SMEM>>>(
        pqr1, pkr1, pscb, SQ, HD,
        (long)SQ * HD, (long)SQ * HD, (long)SQ * SQ, SCALE, 2);

    // screening + exact fp32 rescore + softmax + sparse PV
    attn_select_kernel<<<dim3(SQ, NH), 128>>>();

    // O projection: bf16x3 HMMA
    gemm3_cp<<<dim3(DM / 128, SQ / 128, 1), 256, GEMM3_SMEM>>>(pat3, pwo3, out, DM, K3P, 0, 0, 0, 1.f, 1);
}